// round 4
// baseline (speedup 1.0000x reference)
#include <cuda_runtime.h>

#define NN 100000
#define EE 3200000
#define FIN 128
#define M8 (NN * 8)            // sharded counter count
#define NBLK2 1563             // ceil(M8/512)
#define GEMM1_BLKS 782         // ceil(NN/128)
#define HIST_BLKS 12500        // ceil(EE/256)
#define MAXD1 48
#define MAXD2 48
#define L2E 1.44269504f

// ---------------- scratch (static device globals; no allocs) ----------------
__device__ int   g_cnt8[M8];      // zero at load; re-zeroed by k_scatter
__device__ int   g_off8[M8 + 1];
__device__ int   g_rank[EE];
__device__ unsigned long long g_lb[NBLK2];  // lookback state (re-zeroed)
__device__ int   g_srcs[EE];
__device__ float g_p[EE];                   // overflow-only attention weights
__device__ float g_xl1[NN * 16];
__device__ float g_xr1[NN * 16];
__device__ float g_lin1[NN * 16];
__device__ float g_h[NN * 16];
__device__ float g_xl2[NN * 8];
__device__ float g_xr2[NN * 8];
__device__ float g_lin2[NN * 8];

__device__ __forceinline__ float ex2f(float x) {
    float y; asm("ex2.approx.f32 %0, %1;" : "=f"(y) : "f"(x)); return y;
}

// -------- fused: histogram w/ rank capture (sharded x8) + layer-1 GEMM ------
__global__ void __launch_bounds__(256) k_histgemm1(
    const int* __restrict__ dst,
    const float* __restrict__ x, const float* __restrict__ Wl,
    const float* __restrict__ Wr, const float* __restrict__ Wlin,
    const float* __restrict__ blin)
{
    __shared__ float sx[128][36];
    __shared__ float sw[32][48];
    int t = threadIdx.x;
    int b = blockIdx.x;

    if (b >= GEMM1_BLKS) {
        // ---- histogram path ----
        int e = (b - GEMM1_BLKS) * 256 + t;
        if (e < EE) {
            int d = dst[e];
            g_rank[e] = atomicAdd(&g_cnt8[d * 8 + (e & 7)], 1);
        }
        return;
    }

    // ---- gemm1: 128 rows x 48 cols; thread: 4 rows x 6 cols; K tile 32 ----
    int cg = t & 7, rg = t >> 3;
    int c0 = cg * 6;
    int rowbase = b * 128;
    float acc[4][6];
#pragma unroll
    for (int i = 0; i < 4; i++)
#pragma unroll
        for (int j = 0; j < 6; j++) acc[i][j] = 0.f;

    for (int kb = 0; kb < FIN; kb += 32) {
#pragma unroll
        for (int n = 0; n < 4; n++) {
            int idx = t + n * 256;
            int r = idx >> 3, k4 = idx & 7;
            int gr = rowbase + r;
            float4 val = make_float4(0.f, 0.f, 0.f, 0.f);
            if (gr < NN) val = *(const float4*)(x + gr * FIN + kb + k4 * 4);
            *(float4*)&sx[r][k4 * 4] = val;
        }
        for (int idx = t; idx < 32 * 48; idx += 256) {
            int k = idx / 48, j = idx % 48;
            int gk = kb + k;
            float val;
            if (j < 16)      val = Wl[gk * 16 + j];
            else if (j < 32) val = Wr[gk * 16 + j - 16];
            else             val = Wlin[gk * 16 + j - 32];
            sw[k][j] = val;
        }
        __syncthreads();
#pragma unroll
        for (int k = 0; k < 32; k += 4) {
            float xv[4][4];
#pragma unroll
            for (int i = 0; i < 4; i++) {
                float4 tmp = *(const float4*)&sx[rg * 4 + i][k];
                xv[i][0] = tmp.x; xv[i][1] = tmp.y; xv[i][2] = tmp.z; xv[i][3] = tmp.w;
            }
#pragma unroll
            for (int kk = 0; kk < 4; kk++) {
                float wv[6];
#pragma unroll
                for (int j = 0; j < 6; j++) wv[j] = sw[k + kk][c0 + j];
#pragma unroll
                for (int i = 0; i < 4; i++)
#pragma unroll
                    for (int j = 0; j < 6; j++)
                        acc[i][j] = fmaf(xv[i][kk], wv[j], acc[i][j]);
            }
        }
        __syncthreads();
    }
#pragma unroll
    for (int i = 0; i < 4; i++) {
        int gr = rowbase + rg * 4 + i;
        if (gr < NN) {
#pragma unroll
            for (int j = 0; j < 6; j++) {
                int c = c0 + j;
                if (c < 16)      g_xl1[gr * 16 + c] = acc[i][j];
                else if (c < 32) g_xr1[gr * 16 + (c - 16)] = acc[i][j];
                else             g_lin1[gr * 16 + (c - 32)] = acc[i][j] + blin[c - 32];
            }
        }
    }
}

// ---------------- single-pass lookback scan over sharded counters -----------
__global__ void __launch_bounds__(512) k_scan() {
    int t = threadIdx.x, b = blockIdx.x;
    int i = b * 512 + t;
    int v = (i < M8) ? g_cnt8[i] : 0;
    int lane = t & 31, wid = t >> 5;
    int incl = v;
#pragma unroll
    for (int o = 1; o < 32; o <<= 1) {
        int u = __shfl_up_sync(0xffffffffu, incl, o);
        if (lane >= o) incl += u;
    }
    __shared__ int ws[16];
    __shared__ int s_pfx;
    if (lane == 31) ws[wid] = incl;
    __syncthreads();
    if (t < 16) {
        int xw = ws[t];
#pragma unroll
        for (int o = 1; o < 16; o <<= 1) {
            int u = __shfl_up_sync(0x0000ffffu, xw, o);
            if (t >= o) xw += u;
        }
        ws[t] = xw;
    }
    __syncthreads();
    if (wid > 0) incl += ws[wid - 1];
    if (t == 511) {
        atomicExch(&g_lb[b], (1ull << 32) | (unsigned)incl);
        int pfx = 0;
        for (int j = b - 1; j >= 0;) {
            unsigned long long u = atomicAdd(&g_lb[j], 0ull);
            unsigned f = (unsigned)(u >> 32);
            if (f == 0u) continue;
            pfx += (int)(u & 0xffffffffu);
            if (f == 2u) break;
            --j;
        }
        atomicExch(&g_lb[b], (2ull << 32) | (unsigned)(pfx + incl));
        s_pfx = pfx;
    }
    __syncthreads();
    if (i < M8) g_off8[i + 1] = incl + s_pfx;
    if (i == 0) g_off8[0] = 0;
}

// ---------------- scatter (atomic-free) + reset state for next call ---------
__global__ void k_scatter(const int* __restrict__ src, const int* __restrict__ dst) {
    int e = blockIdx.x * blockDim.x + threadIdx.x;
    if (e < EE) {
        int d = dst[e];
        g_srcs[g_off8[d * 8 + (e & 7)] + g_rank[e]] = src[e];
    }
    if (e < M8) g_cnt8[e] = 0;
    if (e < NBLK2) g_lb[e] = 0ull;
}

// ---------------- edge kernel layer 1: warp/node, 4 lanes/edge --------------
__global__ void __launch_bounds__(256) k_edge1(
    const float* __restrict__ att, const float* __restrict__ bias,
    const float* __restrict__ tptr)
{
    __shared__ float4 sm_m[8][MAXD1][4];
    __shared__ float  sm_p[8][MAXD1];
    int w = threadIdx.x >> 5;
    int lane = threadIdx.x & 31;
    int node = blockIdx.x * 8 + w;
    if (node >= NN) return;
    int q = lane & 3, e8 = lane >> 2;
    int beg = g_off8[node * 8], end = g_off8[node * 8 + 8];
    int deg = end - beg;
    float tval = tptr[0];
    float4 aa = *(const float4*)(att + q * 4);
    aa.x *= L2E; aa.y *= L2E; aa.z *= L2E; aa.w *= L2E;
    float4 xr = *(const float4*)(g_xr1 + node * 16 + q * 4);
    int nfull = deg >> 3, rem = deg & 7;

    // ---- pass 1: full groups (no predication) ----
    float S = 0.f;
    int k = beg + e8;
    for (int it = 0; it < nfull; it++, k += 8) {
        int s = g_srcs[k];
        float4 mq = *(const float4*)(g_xl1 + s * 16 + q * 4);
        float y0 = mq.x + xr.x; y0 = fmaxf(y0, 0.2f * y0);
        float y1 = mq.y + xr.y; y1 = fmaxf(y1, 0.2f * y1);
        float y2 = mq.z + xr.z; y2 = fmaxf(y2, 0.2f * y2);
        float y3 = mq.w + xr.w; y3 = fmaxf(y3, 0.2f * y3);
        float sc = y0 * aa.x;
        sc = fmaf(y1, aa.y, sc);
        sc = fmaf(y2, aa.z, sc);
        sc = fmaf(y3, aa.w, sc);
        sc += __shfl_xor_sync(0xffffffffu, sc, 1);
        sc += __shfl_xor_sync(0xffffffffu, sc, 2);
        float p = ex2f(sc);
        if (it < MAXD1 / 8) {
            sm_m[w][it * 8 + e8][q] = mq;
            if (q == 0) sm_p[w][it * 8 + e8] = p;
        } else {
            g_p[k] = p;   // all quad lanes write identical value (benign)
        }
        S += p;
    }
    // ---- pass 1: remainder (masked) ----
    if (rem) {
        bool v = e8 < rem;
        int s = v ? g_srcs[k] : 0;
        float4 mq = make_float4(0.f, 0.f, 0.f, 0.f);
        if (v) mq = *(const float4*)(g_xl1 + s * 16 + q * 4);
        float y0 = mq.x + xr.x; y0 = fmaxf(y0, 0.2f * y0);
        float y1 = mq.y + xr.y; y1 = fmaxf(y1, 0.2f * y1);
        float y2 = mq.z + xr.z; y2 = fmaxf(y2, 0.2f * y2);
        float y3 = mq.w + xr.w; y3 = fmaxf(y3, 0.2f * y3);
        float sc = y0 * aa.x;
        sc = fmaf(y1, aa.y, sc);
        sc = fmaf(y2, aa.z, sc);
        sc = fmaf(y3, aa.w, sc);
        sc += __shfl_xor_sync(0xffffffffu, sc, 1);
        sc += __shfl_xor_sync(0xffffffffu, sc, 2);
        float p = v ? ex2f(sc) : 0.f;
        if (nfull < MAXD1 / 8) {
            sm_m[w][nfull * 8 + e8][q] = mq;
            if (q == 0) sm_p[w][nfull * 8 + e8] = p;
        } else if (v) {
            g_p[k] = p;
        }
        S += p;
    }
#pragma unroll
    for (int o = 16; o; o >>= 1) S += __shfl_xor_sync(0xffffffffu, S, o);
    float rinv = __fdividef(4.f, S);   // S counted 4x per edge
    float tl2e = tval * L2E;
    __syncwarp();

    // ---- pass 2: cached full groups (no predication, no gathers) ----
    float4 num = make_float4(0.f, 0.f, 0.f, 0.f);
    float4 den = make_float4(0.f, 0.f, 0.f, 0.f);
    int itc = nfull < MAXD1 / 8 ? nfull : MAXD1 / 8;
    k = beg + e8;
    for (int it = 0; it < itc; it++, k += 8) {
        float4 mq = sm_m[w][it * 8 + e8][q];
        float p = sm_p[w][it * 8 + e8];
        float a = p * rinv;
        float we = a * tl2e;
        float e0 = ex2f(mq.x * we);
        float e1 = ex2f(mq.y * we);
        float e2 = ex2f(mq.z * we);
        float e3 = ex2f(mq.w * we);
        den.x += e0; den.y += e1; den.z += e2; den.w += e3;
        num.x = fmaf(e0, mq.x * a, num.x);
        num.y = fmaf(e1, mq.y * a, num.y);
        num.z = fmaf(e2, mq.z * a, num.z);
        num.w = fmaf(e3, mq.w * a, num.w);
    }
    // ---- pass 2: overflow full groups (rare) ----
    for (int it = itc; it < nfull; it++, k += 8) {
        int s = g_srcs[k];
        float4 mq = *(const float4*)(g_xl1 + s * 16 + q * 4);
        float p = g_p[k];
        float a = p * rinv;
        float we = a * tl2e;
        float e0 = ex2f(mq.x * we);
        float e1 = ex2f(mq.y * we);
        float e2 = ex2f(mq.z * we);
        float e3 = ex2f(mq.w * we);
        den.x += e0; den.y += e1; den.z += e2; den.w += e3;
        num.x = fmaf(e0, mq.x * a, num.x);
        num.y = fmaf(e1, mq.y * a, num.y);
        num.z = fmaf(e2, mq.z * a, num.z);
        num.w = fmaf(e3, mq.w * a, num.w);
    }
    // ---- pass 2: remainder (masked) ----
    if (rem) {
        bool v = e8 < rem;
        float vm = v ? 1.f : 0.f;
        float4 mq; float p;
        if (nfull < MAXD1 / 8) {
            mq = sm_m[w][nfull * 8 + e8][q];
            p = sm_p[w][nfull * 8 + e8];
        } else {
            mq = make_float4(0.f, 0.f, 0.f, 0.f);
            p = 0.f;
            if (v) {
                int s = g_srcs[k];
                mq = *(const float4*)(g_xl1 + s * 16 + q * 4);
                p = g_p[k];
            }
        }
        float a = p * rinv;
        float we = a * tl2e;
        float e0 = ex2f(mq.x * we) * vm;
        float e1 = ex2f(mq.y * we) * vm;
        float e2 = ex2f(mq.z * we) * vm;
        float e3 = ex2f(mq.w * we) * vm;
        den.x += e0; den.y += e1; den.z += e2; den.w += e3;
        num.x = fmaf(e0, mq.x * a, num.x);
        num.y = fmaf(e1, mq.y * a, num.y);
        num.z = fmaf(e2, mq.z * a, num.z);
        num.w = fmaf(e3, mq.w * a, num.w);
    }
#pragma unroll
    for (int o = 4; o < 32; o <<= 1) {
        num.x += __shfl_xor_sync(0xffffffffu, num.x, o);
        num.y += __shfl_xor_sync(0xffffffffu, num.y, o);
        num.z += __shfl_xor_sync(0xffffffffu, num.z, o);
        num.w += __shfl_xor_sync(0xffffffffu, num.w, o);
        den.x += __shfl_xor_sync(0xffffffffu, den.x, o);
        den.y += __shfl_xor_sync(0xffffffffu, den.y, o);
        den.z += __shfl_xor_sync(0xffffffffu, den.z, o);
        den.w += __shfl_xor_sync(0xffffffffu, den.w, o);
    }
    if (e8 == 0) {
        float4 b4 = *(const float4*)(bias + q * 4);
        float4 l4 = *(const float4*)(g_lin1 + node * 16 + q * 4);
        float4 o4;
        float g0 = (den.x > 0.f) ? __fdividef(num.x, den.x) : 0.f;
        float g1 = (den.y > 0.f) ? __fdividef(num.y, den.y) : 0.f;
        float g2v = (den.z > 0.f) ? __fdividef(num.z, den.z) : 0.f;
        float g3 = (den.w > 0.f) ? __fdividef(num.w, den.w) : 0.f;
        o4.x = fmaxf(g0 + b4.x + l4.x, 0.f);
        o4.y = fmaxf(g1 + b4.y + l4.y, 0.f);
        o4.z = fmaxf(g2v + b4.z + l4.z, 0.f);
        o4.w = fmaxf(g3 + b4.w + l4.w, 0.f);
        *(float4*)(g_h + node * 16 + q * 4) = o4;
    }
}

// ---------------- layer-2 node GEMM ----------------
__global__ void __launch_bounds__(256) k_gemm2(
    const float* __restrict__ Wl, const float* __restrict__ Wr,
    const float* __restrict__ Wlin, const float* __restrict__ blin)
{
    __shared__ float sw[16 * 24];
    int t = threadIdx.x;
    for (int idx = t; idx < 16 * 24; idx += 256) {
        int k = idx / 24, j = idx % 24;
        float v;
        if (j < 8)       v = Wl[k * 8 + j];
        else if (j < 16) v = Wr[k * 8 + j - 8];
        else             v = Wlin[k * 8 + j - 16];
        sw[idx] = v;
    }
    __syncthreads();
    int i = blockIdx.x * blockDim.x + t;
    if (i >= NN) return;
    const float4* hp = (const float4*)(g_h + i * 16);
    float4 q0 = hp[0], q1 = hp[1], q2 = hp[2], q3 = hp[3];
    float h[16] = {q0.x, q0.y, q0.z, q0.w, q1.x, q1.y, q1.z, q1.w,
                   q2.x, q2.y, q2.z, q2.w, q3.x, q3.y, q3.z, q3.w};
    float acc[24];
#pragma unroll
    for (int j = 0; j < 24; j++) acc[j] = 0.f;
#pragma unroll
    for (int k = 0; k < 16; k++) {
        float hv = h[k];
#pragma unroll
        for (int j = 0; j < 24; j++) acc[j] = fmaf(hv, sw[k * 24 + j], acc[j]);
    }
#pragma unroll
    for (int j = 0; j < 8; j++) {
        g_xl2[i * 8 + j] = acc[j];
        g_xr2[i * 8 + j] = acc[8 + j];
        g_lin2[i * 8 + j] = acc[16 + j] + blin[j];
    }
}

// ------- edge kernel layer 2 (2 lanes/edge) + fused MLP head + log_sigmoid --
__global__ void __launch_bounds__(256) k_edge2h(
    const float* __restrict__ att, const float* __restrict__ bias,
    const float* __restrict__ tptr,
    const float* __restrict__ W3, const float* __restrict__ b3,
    const float* __restrict__ W4, const float* __restrict__ b4,
    const float* __restrict__ W5, const float* __restrict__ b5,
    const float* __restrict__ Wout, const float* __restrict__ bout,
    float* __restrict__ out)
{
    __shared__ float4 sm_m[8][MAXD2][2];
    __shared__ float  sm_p[8][MAXD2];
    int w = threadIdx.x >> 5;
    int lane = threadIdx.x & 31;
    int node = blockIdx.x * 8 + w;
    if (node >= NN) return;
    int q = lane & 1, e16 = lane >> 1;
    int beg = g_off8[node * 8], end = g_off8[node * 8 + 8];
    int deg = end - beg;
    float tval = tptr[0];
    float4 aa = *(const float4*)(att + q * 4);
    aa.x *= L2E; aa.y *= L2E; aa.z *= L2E; aa.w *= L2E;
    float4 xr = *(const float4*)(g_xr2 + node * 8 + q * 4);
    int nfull = deg >> 4, rem = deg & 15;

    float S = 0.f;
    int k = beg + e16;
    for (int it = 0; it < nfull; it++, k += 16) {
        int s = g_srcs[k];
        float4 mq = *(const float4*)(g_xl2 + s * 8 + q * 4);
        float y0 = mq.x + xr.x; y0 = fmaxf(y0, 0.2f * y0);
        float y1 = mq.y + xr.y; y1 = fmaxf(y1, 0.2f * y1);
        float y2 = mq.z + xr.z; y2 = fmaxf(y2, 0.2f * y2);
        float y3 = mq.w + xr.w; y3 = fmaxf(y3, 0.2f * y3);
        float sc = y0 * aa.x;
        sc = fmaf(y1, aa.y, sc);
        sc = fmaf(y2, aa.z, sc);
        sc = fmaf(y3, aa.w, sc);
        sc += __shfl_xor_sync(0xffffffffu, sc, 1);
        float p = ex2f(sc);
        if (it < MAXD2 / 16) {
            sm_m[w][it * 16 + e16][q] = mq;
            if (q == 0) sm_p[w][it * 16 + e16] = p;
        } else {
            g_p[k] = p;
        }
        S += p;
    }
    if (rem) {
        bool v = e16 < rem;
        int s = v ? g_srcs[k] : 0;
        float4 mq = make_float4(0.f, 0.f, 0.f, 0.f);
        if (v) mq = *(const float4*)(g_xl2 + s * 8 + q * 4);
        float y0 = mq.x + xr.x; y0 = fmaxf(y0, 0.2f * y0);
        float y1 = mq.y + xr.y; y1 = fmaxf(y1, 0.2f * y1);
        float y2 = mq.z + xr.z; y2 = fmaxf(y2, 0.2f * y2);
        float y3 = mq.w + xr.w; y3 = fmaxf(y3, 0.2f * y3);
        float sc = y0 * aa.x;
        sc = fmaf(y1, aa.y, sc);
        sc = fmaf(y2, aa.z, sc);
        sc = fmaf(y3, aa.w, sc);
        sc += __shfl_xor_sync(0xffffffffu, sc, 1);
        float p = v ? ex2f(sc) : 0.f;
        if (nfull < MAXD2 / 16) {
            sm_m[w][nfull * 16 + e16][q] = mq;
            if (q == 0) sm_p[w][nfull * 16 + e16] = p;
        } else if (v) {
            g_p[k] = p;
        }
        S += p;
    }
#pragma unroll
    for (int o = 16; o; o >>= 1) S += __shfl_xor_sync(0xffffffffu, S, o);
    float rinv = __fdividef(2.f, S);   // S counted 2x per edge
    float tl2e = tval * L2E;
    __syncwarp();

    float4 num = make_float4(0.f, 0.f, 0.f, 0.f);
    float4 den = make_float4(0.f, 0.f, 0.f, 0.f);
    int itc = nfull < MAXD2 / 16 ? nfull : MAXD2 / 16;
    k = beg + e16;
    for (int it = 0; it < itc; it++, k += 16) {
        float4 mq = sm_m[w][it * 16 + e16][q];
        float p = sm_p[w][it * 16 + e16];
        float a = p * rinv;
        float we = a * tl2e;
        float e0 = ex2f(mq.x * we);
        float e1 = ex2f(mq.y * we);
        float e2 = ex2f(mq.z * we);
        float e3 = ex2f(mq.w * we);
        den.x += e0; den.y += e1; den.z += e2; den.w += e3;
        num.x = fmaf(e0, mq.x * a, num.x);
        num.y = fmaf(e1, mq.y * a, num.y);
        num.z = fmaf(e2, mq.z * a, num.z);
        num.w = fmaf(e3, mq.w * a, num.w);
    }
    for (int it = itc; it < nfull; it++, k += 16) {
        int s = g_srcs[k];
        float4 mq = *(const float4*)(g_xl2 + s * 8 + q * 4);
        float p = g_p[k];
        float a = p * rinv;
        float we = a * tl2e;
        float e0 = ex2f(mq.x * we);
        float e1 = ex2f(mq.y * we);
        float e2 = ex2f(mq.z * we);
        float e3 = ex2f(mq.w * we);
        den.x += e0; den.y += e1; den.z += e2; den.w += e3;
        num.x = fmaf(e0, mq.x * a, num.x);
        num.y = fmaf(e1, mq.y * a, num.y);
        num.z = fmaf(e2, mq.z * a, num.z);
        num.w = fmaf(e3, mq.w * a, num.w);
    }
    if (rem) {
        bool v = e16 < rem;
        float vm = v ? 1.f : 0.f;
        float4 mq; float p;
        if (nfull < MAXD2 / 16) {
            mq = sm_m[w][nfull * 16 + e16][q];
            p = sm_p[w][nfull * 16 + e16];
        } else {
            mq = make_float4(0.f, 0.f, 0.f, 0.f);
            p = 0.f;
            if (v) {
                int s = g_srcs[k];
                mq = *(const float4*)(g_xl2 + s * 8 + q * 4);
                p = g_p[k];
            }
        }
        float a = p * rinv;
        float we = a * tl2e;
        float e0 = ex2f(mq.x * we) * vm;
        float e1 = ex2f(mq.y * we) * vm;
        float e2 = ex2f(mq.z * we) * vm;
        float e3 = ex2f(mq.w * we) * vm;
        den.x += e0; den.y += e1; den.z += e2; den.w += e3;
        num.x = fmaf(e0, mq.x * a, num.x);
        num.y = fmaf(e1, mq.y * a, num.y);
        num.z = fmaf(e2, mq.z * a, num.z);
        num.w = fmaf(e3, mq.w * a, num.w);
    }
#pragma unroll
    for (int o = 2; o < 32; o <<= 1) {
        num.x += __shfl_xor_sync(0xffffffffu, num.x, o);
        num.y += __shfl_xor_sync(0xffffffffu, num.y, o);
        num.z += __shfl_xor_sync(0xffffffffu, num.z, o);
        num.w += __shfl_xor_sync(0xffffffffu, num.w, o);
        den.x += __shfl_xor_sync(0xffffffffu, den.x, o);
        den.y += __shfl_xor_sync(0xffffffffu, den.y, o);
        den.z += __shfl_xor_sync(0xffffffffu, den.z, o);
        den.w += __shfl_xor_sync(0xffffffffu, den.w, o);
    }

    // ---- fused head: lanes pair via q ----
    float4 b4v = *(const float4*)(bias + q * 4);
    float4 l4 = *(const float4*)(g_lin2 + node * 8 + q * 4);
    float hq[4];
    {
        float g0 = (den.x > 0.f) ? __fdividef(num.x, den.x) : 0.f;
        float g1 = (den.y > 0.f) ? __fdividef(num.y, den.y) : 0.f;
        float g2v = (den.z > 0.f) ? __fdividef(num.z, den.z) : 0.f;
        float g3 = (den.w > 0.f) ? __fdividef(num.w, den.w) : 0.f;
        hq[0] = fmaxf(g0 + b4v.x + l4.x, 0.f);
        hq[1] = fmaxf(g1 + b4v.y + l4.y, 0.f);
        hq[2] = fmaxf(g2v + b4v.z + l4.z, 0.f);
        hq[3] = fmaxf(g3 + b4v.w + l4.w, 0.f);
    }
    float part[8];
#pragma unroll
    for (int c = 0; c < 8; c++) {
        float acc = 0.f;
#pragma unroll
        for (int j = 0; j < 4; j++)
            acc = fmaf(hq[j], W3[(4 * q + j) * 8 + c], acc);
        part[c] = acc;
    }
#pragma unroll
    for (int c = 0; c < 8; c++)
        part[c] += __shfl_xor_sync(0xffffffffu, part[c], 1);
    if (lane == 0) {
        float s4 = b4[0];
#pragma unroll
        for (int c = 0; c < 8; c++) {
            float z = part[c] + b3[c];
            z = z > 0.f ? z : 0.f;
            s4 = fmaf(z, W4[c], s4);
        }
        s4 = s4 > 0.f ? s4 : 0.f;
        float s5 = W5[0] * s4 + b5[0];
        s5 = s5 > 0.f ? s5 : 0.f;
        float xo = Wout[0] * s5 + bout[0];
        float ls = (xo >= 0.f) ? -log1pf(expf(-xo)) : (xo - log1pf(expf(xo)));
        out[node] = ls;
    }
}

// ---------------- launch ----------------
extern "C" void kernel_launch(void* const* d_in, const int* in_sizes, int n_in,
                              void* d_out, int out_size)
{
    const float* x    = (const float*)d_in[0];
    const int*   ei   = (const int*)d_in[1];
    const int*   src  = ei;
    const int*   dst  = ei + EE;
    const float* Wl1  = (const float*)d_in[3];
    const float* Wr1  = (const float*)d_in[4];
    const float* att1 = (const float*)d_in[5];
    const float* b1   = (const float*)d_in[6];
    const float* Wlin1= (const float*)d_in[7];
    const float* blin1= (const float*)d_in[8];
    const float* Wl2  = (const float*)d_in[9];
    const float* Wr2  = (const float*)d_in[10];
    const float* att2 = (const float*)d_in[11];
    const float* b2   = (const float*)d_in[12];
    const float* Wlin2= (const float*)d_in[13];
    const float* blin2= (const float*)d_in[14];
    const float* t    = (const float*)d_in[15];
    const float* W3   = (const float*)d_in[16];
    const float* b3   = (const float*)d_in[17];
    const float* W4   = (const float*)d_in[18];
    const float* b4   = (const float*)d_in[19];
    const float* W5   = (const float*)d_in[20];
    const float* b5   = (const float*)d_in[21];
    const float* Wout = (const float*)d_in[22];
    const float* bout = (const float*)d_in[23];
    float* out = (float*)d_out;

    // 0: fused sharded histogram + layer-1 GEMM (different pipes, overlapped)
    k_histgemm1<<<GEMM1_BLKS + HIST_BLKS, 256>>>(dst, x, Wl1, Wr1, Wlin1, blin1);
    // 1: single-pass lookback scan over 800K sharded counters
    k_scan<<<NBLK2, 512>>>();
    // 2: atomic-free scatter + reset counters/lookback for next call
    k_scatter<<<HIST_BLKS, 256>>>(src, dst);
    // 3: edge layer 1  (<- profiled slot)
    k_edge1<<<(NN + 7) / 8, 256>>>(att1, b1, t);
    // 4: layer-2 GEMM (pool is identity: batch = arange(N))
    k_gemm2<<<(NN + 255) / 256, 256>>>(Wl2, Wr2, Wlin2, blin2);
    // 5: edge layer 2 + fused MLP head
    k_edge2h<<<(NN + 7) / 8, 256>>>(att2, b2, t, W3, b3, W4, b4, W5, b5, Wout, bout, out);
}

// round 5
// speedup vs baseline: 1.0633x; 1.0633x over previous
#include <cuda_runtime.h>

#define NN 100000
#define EE 3200000
#define FIN 128
#define CAP 128                // fixed bucket capacity per node
#define GEMM1_BLKS 782         // ceil(NN/128)
#define HIST_BLKS 12500        // ceil(EE/256)
#define MAXD1 48
#define MAXD2 48
#define L2E 1.44269504f

// ---------------- scratch (static device globals; no allocs) ----------------
__device__ int   g_cnt[NN];          // zero at load; re-zeroed by k_edge2h
__device__ int   g_srcs[NN * CAP];   // fixed-capacity CSR buckets
__device__ int   g_ovf_cnt;          // overflow count (build writes, gemm2 swaps)
__device__ int   g_ovf_cnt2;         // snapshot for edge2h
__device__ int   g_ovfd[EE];         // overflow dst (cold)
__device__ int   g_ovfs[EE];         // overflow src (cold)
__device__ float g_p[NN * CAP];      // warm-overflow attention weights (deg>MAXD)
__device__ float g_xl1[NN * 16];
__device__ float g_xr1[NN * 16];
__device__ float g_lin1[NN * 16];
__device__ float g_h[NN * 16];
__device__ float g_xl2[NN * 8];
__device__ float g_xr2[NN * 8];
__device__ float g_lin2[NN * 8];

__device__ __forceinline__ float ex2f(float x) {
    float y; asm("ex2.approx.f32 %0, %1;" : "=f"(y) : "f"(x)); return y;
}

// ---- fused build: layer-1 GEMM (blocks 0..781) + bucket scatter (rest) -----
__global__ void __launch_bounds__(256) k_build(
    const int* __restrict__ src, const int* __restrict__ dst,
    const float* __restrict__ x, const float* __restrict__ Wl,
    const float* __restrict__ Wr, const float* __restrict__ Wlin,
    const float* __restrict__ blin)
{
    __shared__ float sx[128][36];
    __shared__ float sw[32][48];
    int t = threadIdx.x;
    int b = blockIdx.x;

    if (b >= GEMM1_BLKS) {
        // ---- direct bucket scatter: hist + placement in one pass ----
        int e = (b - GEMM1_BLKS) * 256 + t;
        if (e < EE) {
            int d = dst[e];
            int r = atomicAdd(&g_cnt[d], 1);
            if (r < CAP) {
                g_srcs[d * CAP + r] = src[e];
            } else {
                int o = atomicAdd(&g_ovf_cnt, 1);
                g_ovfd[o] = d;
                g_ovfs[o] = src[e];
            }
        }
        return;
    }

    // ---- gemm1: 128 rows x 48 cols; thread: 4 rows x 6 cols; K tile 32 ----
    int cg = t & 7, rg = t >> 3;
    int c0 = cg * 6;
    int rowbase = b * 128;
    float acc[4][6];
#pragma unroll
    for (int i = 0; i < 4; i++)
#pragma unroll
        for (int j = 0; j < 6; j++) acc[i][j] = 0.f;

    for (int kb = 0; kb < FIN; kb += 32) {
#pragma unroll
        for (int n = 0; n < 4; n++) {
            int idx = t + n * 256;
            int r = idx >> 3, k4 = idx & 7;
            int gr = rowbase + r;
            float4 val = make_float4(0.f, 0.f, 0.f, 0.f);
            if (gr < NN) val = *(const float4*)(x + gr * FIN + kb + k4 * 4);
            *(float4*)&sx[r][k4 * 4] = val;
        }
        for (int idx = t; idx < 32 * 48; idx += 256) {
            int k = idx / 48, j = idx % 48;
            int gk = kb + k;
            float val;
            if (j < 16)      val = Wl[gk * 16 + j];
            else if (j < 32) val = Wr[gk * 16 + j - 16];
            else             val = Wlin[gk * 16 + j - 32];
            sw[k][j] = val;
        }
        __syncthreads();
#pragma unroll
        for (int k = 0; k < 32; k += 4) {
            float xv[4][4];
#pragma unroll
            for (int i = 0; i < 4; i++) {
                float4 tmp = *(const float4*)&sx[rg * 4 + i][k];
                xv[i][0] = tmp.x; xv[i][1] = tmp.y; xv[i][2] = tmp.z; xv[i][3] = tmp.w;
            }
#pragma unroll
            for (int kk = 0; kk < 4; kk++) {
                float wv[6];
#pragma unroll
                for (int j = 0; j < 6; j++) wv[j] = sw[k + kk][c0 + j];
#pragma unroll
                for (int i = 0; i < 4; i++)
#pragma unroll
                    for (int j = 0; j < 6; j++)
                        acc[i][j] = fmaf(xv[i][kk], wv[j], acc[i][j]);
            }
        }
        __syncthreads();
    }
#pragma unroll
    for (int i = 0; i < 4; i++) {
        int gr = rowbase + rg * 4 + i;
        if (gr < NN) {
#pragma unroll
            for (int j = 0; j < 6; j++) {
                int c = c0 + j;
                if (c < 16)      g_xl1[gr * 16 + c] = acc[i][j];
                else if (c < 32) g_xr1[gr * 16 + (c - 16)] = acc[i][j];
                else             g_lin1[gr * 16 + (c - 32)] = acc[i][j] + blin[c - 32];
            }
        }
    }
}

// ---------------- edge kernel layer 1: warp/node, 4 lanes/edge --------------
__global__ void __launch_bounds__(256) k_edge1(
    const float* __restrict__ att, const float* __restrict__ bias,
    const float* __restrict__ tptr)
{
    __shared__ float4 sm_m[8][MAXD1][4];
    __shared__ float  sm_p[8][MAXD1];
    int w = threadIdx.x >> 5;
    int lane = threadIdx.x & 31;
    int node = blockIdx.x * 8 + w;
    if (node >= NN) return;
    int q = lane & 3, e8 = lane >> 2;
    int deg = g_cnt[node];
    int degf = deg < CAP ? deg : CAP;
    int beg = node * CAP;
    float tval = tptr[0];
    float4 aa = *(const float4*)(att + q * 4);
    aa.x *= L2E; aa.y *= L2E; aa.z *= L2E; aa.w *= L2E;
    float4 xr = *(const float4*)(g_xr1 + node * 16 + q * 4);
    int nfull = degf >> 3, rem = degf & 7;

    // ---- pass 1: full groups (no predication) ----
    float S = 0.f;
    int k = beg + e8;
    for (int it = 0; it < nfull; it++, k += 8) {
        int s = g_srcs[k];
        float4 mq = *(const float4*)(g_xl1 + s * 16 + q * 4);
        float y0 = mq.x + xr.x; y0 = fmaxf(y0, 0.2f * y0);
        float y1 = mq.y + xr.y; y1 = fmaxf(y1, 0.2f * y1);
        float y2 = mq.z + xr.z; y2 = fmaxf(y2, 0.2f * y2);
        float y3 = mq.w + xr.w; y3 = fmaxf(y3, 0.2f * y3);
        float sc = y0 * aa.x;
        sc = fmaf(y1, aa.y, sc);
        sc = fmaf(y2, aa.z, sc);
        sc = fmaf(y3, aa.w, sc);
        sc += __shfl_xor_sync(0xffffffffu, sc, 1);
        sc += __shfl_xor_sync(0xffffffffu, sc, 2);
        float p = ex2f(sc);
        if (it < MAXD1 / 8) {
            sm_m[w][it * 8 + e8][q] = mq;
            if (q == 0) sm_p[w][it * 8 + e8] = p;
        } else {
            g_p[k] = p;   // quad-duplicated write (benign)
        }
        S += p;
    }
    // ---- pass 1: remainder (masked) ----
    if (rem) {
        bool v = e8 < rem;
        int s = v ? g_srcs[k] : 0;
        float4 mq = make_float4(0.f, 0.f, 0.f, 0.f);
        if (v) mq = *(const float4*)(g_xl1 + s * 16 + q * 4);
        float y0 = mq.x + xr.x; y0 = fmaxf(y0, 0.2f * y0);
        float y1 = mq.y + xr.y; y1 = fmaxf(y1, 0.2f * y1);
        float y2 = mq.z + xr.z; y2 = fmaxf(y2, 0.2f * y2);
        float y3 = mq.w + xr.w; y3 = fmaxf(y3, 0.2f * y3);
        float sc = y0 * aa.x;
        sc = fmaf(y1, aa.y, sc);
        sc = fmaf(y2, aa.z, sc);
        sc = fmaf(y3, aa.w, sc);
        sc += __shfl_xor_sync(0xffffffffu, sc, 1);
        sc += __shfl_xor_sync(0xffffffffu, sc, 2);
        float p = v ? ex2f(sc) : 0.f;
        if (nfull < MAXD1 / 8) {
            sm_m[w][nfull * 8 + e8][q] = mq;
            if (q == 0) sm_p[w][nfull * 8 + e8] = p;
        } else if (v) {
            g_p[k] = p;
        }
        S += p;
    }
    // ---- pass 1: overflow list (cold; never taken for this data) ----
    if (deg > CAP) {
        int ovfn = g_ovf_cnt;
        for (int i = 0; i < ovfn; i++) {
            if (g_ovfd[i] == node) {
                float4 mq = make_float4(0.f, 0.f, 0.f, 0.f);
                if (e8 == 0) {
                    int s = g_ovfs[i];
                    mq = *(const float4*)(g_xl1 + s * 16 + q * 4);
                }
                float y0 = mq.x + xr.x; y0 = fmaxf(y0, 0.2f * y0);
                float y1 = mq.y + xr.y; y1 = fmaxf(y1, 0.2f * y1);
                float y2 = mq.z + xr.z; y2 = fmaxf(y2, 0.2f * y2);
                float y3 = mq.w + xr.w; y3 = fmaxf(y3, 0.2f * y3);
                float sc = y0 * aa.x;
                sc = fmaf(y1, aa.y, sc);
                sc = fmaf(y2, aa.z, sc);
                sc = fmaf(y3, aa.w, sc);
                sc += __shfl_xor_sync(0xffffffffu, sc, 1);
                sc += __shfl_xor_sync(0xffffffffu, sc, 2);
                if (e8 == 0) S += ex2f(sc);
            }
        }
    }
#pragma unroll
    for (int o = 16; o; o >>= 1) S += __shfl_xor_sync(0xffffffffu, S, o);
    float rinv = __fdividef(4.f, S);   // S counted 4x per edge
    float tl2e = tval * L2E;
    __syncwarp();

    // ---- pass 2: cached full groups ----
    float4 num = make_float4(0.f, 0.f, 0.f, 0.f);
    float4 den = make_float4(0.f, 0.f, 0.f, 0.f);
    int itc = nfull < MAXD1 / 8 ? nfull : MAXD1 / 8;
    k = beg + e8;
    for (int it = 0; it < itc; it++, k += 8) {
        float4 mq = sm_m[w][it * 8 + e8][q];
        float p = sm_p[w][it * 8 + e8];
        float a = p * rinv;
        float we = a * tl2e;
        float e0 = ex2f(mq.x * we);
        float e1 = ex2f(mq.y * we);
        float e2 = ex2f(mq.z * we);
        float e3 = ex2f(mq.w * we);
        den.x += e0; den.y += e1; den.z += e2; den.w += e3;
        num.x = fmaf(e0, mq.x * a, num.x);
        num.y = fmaf(e1, mq.y * a, num.y);
        num.z = fmaf(e2, mq.z * a, num.z);
        num.w = fmaf(e3, mq.w * a, num.w);
    }
    // ---- pass 2: warm-overflow full groups (deg in (MAXD1, CAP]) ----
    for (int it = itc; it < nfull; it++, k += 8) {
        int s = g_srcs[k];
        float4 mq = *(const float4*)(g_xl1 + s * 16 + q * 4);
        float p = g_p[k];
        float a = p * rinv;
        float we = a * tl2e;
        float e0 = ex2f(mq.x * we);
        float e1 = ex2f(mq.y * we);
        float e2 = ex2f(mq.z * we);
        float e3 = ex2f(mq.w * we);
        den.x += e0; den.y += e1; den.z += e2; den.w += e3;
        num.x = fmaf(e0, mq.x * a, num.x);
        num.y = fmaf(e1, mq.y * a, num.y);
        num.z = fmaf(e2, mq.z * a, num.z);
        num.w = fmaf(e3, mq.w * a, num.w);
    }
    // ---- pass 2: remainder (masked) ----
    if (rem) {
        bool v = e8 < rem;
        float vm = v ? 1.f : 0.f;
        float4 mq; float p;
        if (nfull < MAXD1 / 8) {
            mq = sm_m[w][nfull * 8 + e8][q];
            p = sm_p[w][nfull * 8 + e8];
        } else {
            mq = make_float4(0.f, 0.f, 0.f, 0.f);
            p = 0.f;
            if (v) {
                int s = g_srcs[k];
                mq = *(const float4*)(g_xl1 + s * 16 + q * 4);
                p = g_p[k];
            }
        }
        float a = p * rinv;
        float we = a * tl2e;
        float e0 = ex2f(mq.x * we) * vm;
        float e1 = ex2f(mq.y * we) * vm;
        float e2 = ex2f(mq.z * we) * vm;
        float e3 = ex2f(mq.w * we) * vm;
        den.x += e0; den.y += e1; den.z += e2; den.w += e3;
        num.x = fmaf(e0, mq.x * a, num.x);
        num.y = fmaf(e1, mq.y * a, num.y);
        num.z = fmaf(e2, mq.z * a, num.z);
        num.w = fmaf(e3, mq.w * a, num.w);
    }
    // ---- pass 2: overflow list (cold) ----
    if (deg > CAP) {
        int ovfn = g_ovf_cnt;
        for (int i = 0; i < ovfn; i++) {
            if (g_ovfd[i] == node) {
                float4 mq = make_float4(0.f, 0.f, 0.f, 0.f);
                if (e8 == 0) {
                    int s = g_ovfs[i];
                    mq = *(const float4*)(g_xl1 + s * 16 + q * 4);
                }
                float y0 = mq.x + xr.x; y0 = fmaxf(y0, 0.2f * y0);
                float y1 = mq.y + xr.y; y1 = fmaxf(y1, 0.2f * y1);
                float y2 = mq.z + xr.z; y2 = fmaxf(y2, 0.2f * y2);
                float y3 = mq.w + xr.w; y3 = fmaxf(y3, 0.2f * y3);
                float sc = y0 * aa.x;
                sc = fmaf(y1, aa.y, sc);
                sc = fmaf(y2, aa.z, sc);
                sc = fmaf(y3, aa.w, sc);
                sc += __shfl_xor_sync(0xffffffffu, sc, 1);
                sc += __shfl_xor_sync(0xffffffffu, sc, 2);
                if (e8 == 0) {
                    float p = ex2f(sc);
                    float a = p * rinv;
                    float we = a * tl2e;
                    float e0 = ex2f(mq.x * we);
                    float e1 = ex2f(mq.y * we);
                    float e2 = ex2f(mq.z * we);
                    float e3 = ex2f(mq.w * we);
                    den.x += e0; den.y += e1; den.z += e2; den.w += e3;
                    num.x = fmaf(e0, mq.x * a, num.x);
                    num.y = fmaf(e1, mq.y * a, num.y);
                    num.z = fmaf(e2, mq.z * a, num.z);
                    num.w = fmaf(e3, mq.w * a, num.w);
                }
            }
        }
    }
#pragma unroll
    for (int o = 4; o < 32; o <<= 1) {
        num.x += __shfl_xor_sync(0xffffffffu, num.x, o);
        num.y += __shfl_xor_sync(0xffffffffu, num.y, o);
        num.z += __shfl_xor_sync(0xffffffffu, num.z, o);
        num.w += __shfl_xor_sync(0xffffffffu, num.w, o);
        den.x += __shfl_xor_sync(0xffffffffu, den.x, o);
        den.y += __shfl_xor_sync(0xffffffffu, den.y, o);
        den.z += __shfl_xor_sync(0xffffffffu, den.z, o);
        den.w += __shfl_xor_sync(0xffffffffu, den.w, o);
    }
    if (e8 == 0) {
        float4 b4 = *(const float4*)(bias + q * 4);
        float4 l4 = *(const float4*)(g_lin1 + node * 16 + q * 4);
        float4 o4;
        float g0 = (den.x > 0.f) ? __fdividef(num.x, den.x) : 0.f;
        float g1 = (den.y > 0.f) ? __fdividef(num.y, den.y) : 0.f;
        float g2v = (den.z > 0.f) ? __fdividef(num.z, den.z) : 0.f;
        float g3 = (den.w > 0.f) ? __fdividef(num.w, den.w) : 0.f;
        o4.x = fmaxf(g0 + b4.x + l4.x, 0.f);
        o4.y = fmaxf(g1 + b4.y + l4.y, 0.f);
        o4.z = fmaxf(g2v + b4.z + l4.z, 0.f);
        o4.w = fmaxf(g3 + b4.w + l4.w, 0.f);
        *(float4*)(g_h + node * 16 + q * 4) = o4;
    }
}

// ---------------- layer-2 node GEMM (+ overflow counter hand-off) -----------
__global__ void __launch_bounds__(256) k_gemm2(
    const float* __restrict__ Wl, const float* __restrict__ Wr,
    const float* __restrict__ Wlin, const float* __restrict__ blin)
{
    if (blockIdx.x == 0 && threadIdx.x == 0) {
        g_ovf_cnt2 = g_ovf_cnt;   // snapshot for edge2h
        g_ovf_cnt = 0;            // ready for next launch
    }
    __shared__ float sw[16 * 24];
    int t = threadIdx.x;
    for (int idx = t; idx < 16 * 24; idx += 256) {
        int k = idx / 24, j = idx % 24;
        float v;
        if (j < 8)       v = Wl[k * 8 + j];
        else if (j < 16) v = Wr[k * 8 + j - 8];
        else             v = Wlin[k * 8 + j - 16];
        sw[idx] = v;
    }
    __syncthreads();
    int i = blockIdx.x * blockDim.x + t;
    if (i >= NN) return;
    const float4* hp = (const float4*)(g_h + i * 16);
    float4 q0 = hp[0], q1 = hp[1], q2 = hp[2], q3 = hp[3];
    float h[16] = {q0.x, q0.y, q0.z, q0.w, q1.x, q1.y, q1.z, q1.w,
                   q2.x, q2.y, q2.z, q2.w, q3.x, q3.y, q3.z, q3.w};
    float acc[24];
#pragma unroll
    for (int j = 0; j < 24; j++) acc[j] = 0.f;
#pragma unroll
    for (int k = 0; k < 16; k++) {
        float hv = h[k];
#pragma unroll
        for (int j = 0; j < 24; j++) acc[j] = fmaf(hv, sw[k * 24 + j], acc[j]);
    }
#pragma unroll
    for (int j = 0; j < 8; j++) {
        g_xl2[i * 8 + j] = acc[j];
        g_xr2[i * 8 + j] = acc[8 + j];
        g_lin2[i * 8 + j] = acc[16 + j] + blin[j];
    }
}

// ------- edge kernel layer 2 (2 lanes/edge) + fused MLP head + log_sigmoid --
__global__ void __launch_bounds__(256) k_edge2h(
    const float* __restrict__ att, const float* __restrict__ bias,
    const float* __restrict__ tptr,
    const float* __restrict__ W3, const float* __restrict__ b3,
    const float* __restrict__ W4, const float* __restrict__ b4,
    const float* __restrict__ W5, const float* __restrict__ b5,
    const float* __restrict__ Wout, const float* __restrict__ bout,
    float* __restrict__ out)
{
    __shared__ float4 sm_m[8][MAXD2][2];
    __shared__ float  sm_p[8][MAXD2];
    int w = threadIdx.x >> 5;
    int lane = threadIdx.x & 31;
    int node = blockIdx.x * 8 + w;
    if (node >= NN) return;
    int q = lane & 1, e16 = lane >> 1;
    int deg = g_cnt[node];
    if (lane == 0) g_cnt[node] = 0;   // reset for next launch (deg already read)
    int degf = deg < CAP ? deg : CAP;
    int beg = node * CAP;
    float tval = tptr[0];
    float4 aa = *(const float4*)(att + q * 4);
    aa.x *= L2E; aa.y *= L2E; aa.z *= L2E; aa.w *= L2E;
    float4 xr = *(const float4*)(g_xr2 + node * 8 + q * 4);
    int nfull = degf >> 4, rem = degf & 15;

    float S = 0.f;
    int k = beg + e16;
    for (int it = 0; it < nfull; it++, k += 16) {
        int s = g_srcs[k];
        float4 mq = *(const float4*)(g_xl2 + s * 8 + q * 4);
        float y0 = mq.x + xr.x; y0 = fmaxf(y0, 0.2f * y0);
        float y1 = mq.y + xr.y; y1 = fmaxf(y1, 0.2f * y1);
        float y2 = mq.z + xr.z; y2 = fmaxf(y2, 0.2f * y2);
        float y3 = mq.w + xr.w; y3 = fmaxf(y3, 0.2f * y3);
        float sc = y0 * aa.x;
        sc = fmaf(y1, aa.y, sc);
        sc = fmaf(y2, aa.z, sc);
        sc = fmaf(y3, aa.w, sc);
        sc += __shfl_xor_sync(0xffffffffu, sc, 1);
        float p = ex2f(sc);
        if (it < MAXD2 / 16) {
            sm_m[w][it * 16 + e16][q] = mq;
            if (q == 0) sm_p[w][it * 16 + e16] = p;
        } else {
            g_p[k] = p;
        }
        S += p;
    }
    if (rem) {
        bool v = e16 < rem;
        int s = v ? g_srcs[k] : 0;
        float4 mq = make_float4(0.f, 0.f, 0.f, 0.f);
        if (v) mq = *(const float4*)(g_xl2 + s * 8 + q * 4);
        float y0 = mq.x + xr.x; y0 = fmaxf(y0, 0.2f * y0);
        float y1 = mq.y + xr.y; y1 = fmaxf(y1, 0.2f * y1);
        float y2 = mq.z + xr.z; y2 = fmaxf(y2, 0.2f * y2);
        float y3 = mq.w + xr.w; y3 = fmaxf(y3, 0.2f * y3);
        float sc = y0 * aa.x;
        sc = fmaf(y1, aa.y, sc);
        sc = fmaf(y2, aa.z, sc);
        sc = fmaf(y3, aa.w, sc);
        sc += __shfl_xor_sync(0xffffffffu, sc, 1);
        float p = v ? ex2f(sc) : 0.f;
        if (nfull < MAXD2 / 16) {
            sm_m[w][nfull * 16 + e16][q] = mq;
            if (q == 0) sm_p[w][nfull * 16 + e16] = p;
        } else if (v) {
            g_p[k] = p;
        }
        S += p;
    }
    // overflow list pass 1 (cold)
    if (deg > CAP) {
        int ovfn = g_ovf_cnt2;
        for (int i = 0; i < ovfn; i++) {
            if (g_ovfd[i] == node) {
                float4 mq = make_float4(0.f, 0.f, 0.f, 0.f);
                if (e16 == 0) {
                    int s = g_ovfs[i];
                    mq = *(const float4*)(g_xl2 + s * 8 + q * 4);
                }
                float y0 = mq.x + xr.x; y0 = fmaxf(y0, 0.2f * y0);
                float y1 = mq.y + xr.y; y1 = fmaxf(y1, 0.2f * y1);
                float y2 = mq.z + xr.z; y2 = fmaxf(y2, 0.2f * y2);
                float y3 = mq.w + xr.w; y3 = fmaxf(y3, 0.2f * y3);
                float sc = y0 * aa.x;
                sc = fmaf(y1, aa.y, sc);
                sc = fmaf(y2, aa.z, sc);
                sc = fmaf(y3, aa.w, sc);
                sc += __shfl_xor_sync(0xffffffffu, sc, 1);
                if (e16 == 0) S += ex2f(sc);
            }
        }
    }
#pragma unroll
    for (int o = 16; o; o >>= 1) S += __shfl_xor_sync(0xffffffffu, S, o);
    float rinv = __fdividef(2.f, S);   // S counted 2x per edge
    float tl2e = tval * L2E;
    __syncwarp();

    float4 num = make_float4(0.f, 0.f, 0.f, 0.f);
    float4 den = make_float4(0.f, 0.f, 0.f, 0.f);
    int itc = nfull < MAXD2 / 16 ? nfull : MAXD2 / 16;
    k = beg + e16;
    for (int it = 0; it < itc; it++, k += 16) {
        float4 mq = sm_m[w][it * 16 + e16][q];
        float p = sm_p[w][it * 16 + e16];
        float a = p * rinv;
        float we = a * tl2e;
        float e0 = ex2f(mq.x * we);
        float e1 = ex2f(mq.y * we);
        float e2 = ex2f(mq.z * we);
        float e3 = ex2f(mq.w * we);
        den.x += e0; den.y += e1; den.z += e2; den.w += e3;
        num.x = fmaf(e0, mq.x * a, num.x);
        num.y = fmaf(e1, mq.y * a, num.y);
        num.z = fmaf(e2, mq.z * a, num.z);
        num.w = fmaf(e3, mq.w * a, num.w);
    }
    for (int it = itc; it < nfull; it++, k += 16) {
        int s = g_srcs[k];
        float4 mq = *(const float4*)(g_xl2 + s * 8 + q * 4);
        float p = g_p[k];
        float a = p * rinv;
        float we = a * tl2e;
        float e0 = ex2f(mq.x * we);
        float e1 = ex2f(mq.y * we);
        float e2 = ex2f(mq.z * we);
        float e3 = ex2f(mq.w * we);
        den.x += e0; den.y += e1; den.z += e2; den.w += e3;
        num.x = fmaf(e0, mq.x * a, num.x);
        num.y = fmaf(e1, mq.y * a, num.y);
        num.z = fmaf(e2, mq.z * a, num.z);
        num.w = fmaf(e3, mq.w * a, num.w);
    }
    if (rem) {
        bool v = e16 < rem;
        float vm = v ? 1.f : 0.f;
        float4 mq; float p;
        if (nfull < MAXD2 / 16) {
            mq = sm_m[w][nfull * 16 + e16][q];
            p = sm_p[w][nfull * 16 + e16];
        } else {
            mq = make_float4(0.f, 0.f, 0.f, 0.f);
            p = 0.f;
            if (v) {
                int s = g_srcs[k];
                mq = *(const float4*)(g_xl2 + s * 8 + q * 4);
                p = g_p[k];
            }
        }
        float a = p * rinv;
        float we = a * tl2e;
        float e0 = ex2f(mq.x * we) * vm;
        float e1 = ex2f(mq.y * we) * vm;
        float e2 = ex2f(mq.z * we) * vm;
        float e3 = ex2f(mq.w * we) * vm;
        den.x += e0; den.y += e1; den.z += e2; den.w += e3;
        num.x = fmaf(e0, mq.x * a, num.x);
        num.y = fmaf(e1, mq.y * a, num.y);
        num.z = fmaf(e2, mq.z * a, num.z);
        num.w = fmaf(e3, mq.w * a, num.w);
    }
    // overflow list pass 2 (cold)
    if (deg > CAP) {
        int ovfn = g_ovf_cnt2;
        for (int i = 0; i < ovfn; i++) {
            if (g_ovfd[i] == node) {
                float4 mq = make_float4(0.f, 0.f, 0.f, 0.f);
                if (e16 == 0) {
                    int s = g_ovfs[i];
                    mq = *(const float4*)(g_xl2 + s * 8 + q * 4);
                }
                float y0 = mq.x + xr.x; y0 = fmaxf(y0, 0.2f * y0);
                float y1 = mq.y + xr.y; y1 = fmaxf(y1, 0.2f * y1);
                float y2 = mq.z + xr.z; y2 = fmaxf(y2, 0.2f * y2);
                float y3 = mq.w + xr.w; y3 = fmaxf(y3, 0.2f * y3);
                float sc = y0 * aa.x;
                sc = fmaf(y1, aa.y, sc);
                sc = fmaf(y2, aa.z, sc);
                sc = fmaf(y3, aa.w, sc);
                sc += __shfl_xor_sync(0xffffffffu, sc, 1);
                if (e16 == 0) {
                    float p = ex2f(sc);
                    float a = p * rinv;
                    float we = a * tl2e;
                    float e0 = ex2f(mq.x * we);
                    float e1 = ex2f(mq.y * we);
                    float e2 = ex2f(mq.z * we);
                    float e3 = ex2f(mq.w * we);
                    den.x += e0; den.y += e1; den.z += e2; den.w += e3;
                    num.x = fmaf(e0, mq.x * a, num.x);
                    num.y = fmaf(e1, mq.y * a, num.y);
                    num.z = fmaf(e2, mq.z * a, num.z);
                    num.w = fmaf(e3, mq.w * a, num.w);
                }
            }
        }
    }
#pragma unroll
    for (int o = 2; o < 32; o <<= 1) {
        num.x += __shfl_xor_sync(0xffffffffu, num.x, o);
        num.y += __shfl_xor_sync(0xffffffffu, num.y, o);
        num.z += __shfl_xor_sync(0xffffffffu, num.z, o);
        num.w += __shfl_xor_sync(0xffffffffu, num.w, o);
        den.x += __shfl_xor_sync(0xffffffffu, den.x, o);
        den.y += __shfl_xor_sync(0xffffffffu, den.y, o);
        den.z += __shfl_xor_sync(0xffffffffu, den.z, o);
        den.w += __shfl_xor_sync(0xffffffffu, den.w, o);
    }

    // ---- fused head: lanes pair via q ----
    float4 b4v = *(const float4*)(bias + q * 4);
    float4 l4 = *(const float4*)(g_lin2 + node * 8 + q * 4);
    float hq[4];
    {
        float g0 = (den.x > 0.f) ? __fdividef(num.x, den.x) : 0.f;
        float g1 = (den.y > 0.f) ? __fdividef(num.y, den.y) : 0.f;
        float g2v = (den.z > 0.f) ? __fdividef(num.z, den.z) : 0.f;
        float g3 = (den.w > 0.f) ? __fdividef(num.w, den.w) : 0.f;
        hq[0] = fmaxf(g0 + b4v.x + l4.x, 0.f);
        hq[1] = fmaxf(g1 + b4v.y + l4.y, 0.f);
        hq[2] = fmaxf(g2v + b4v.z + l4.z, 0.f);
        hq[3] = fmaxf(g3 + b4v.w + l4.w, 0.f);
    }
    float part[8];
#pragma unroll
    for (int c = 0; c < 8; c++) {
        float acc = 0.f;
#pragma unroll
        for (int j = 0; j < 4; j++)
            acc = fmaf(hq[j], W3[(4 * q + j) * 8 + c], acc);
        part[c] = acc;
    }
#pragma unroll
    for (int c = 0; c < 8; c++)
        part[c] += __shfl_xor_sync(0xffffffffu, part[c], 1);
    if (lane == 0) {
        float s4 = b4[0];
#pragma unroll
        for (int c = 0; c < 8; c++) {
            float z = part[c] + b3[c];
            z = z > 0.f ? z : 0.f;
            s4 = fmaf(z, W4[c], s4);
        }
        s4 = s4 > 0.f ? s4 : 0.f;
        float s5 = W5[0] * s4 + b5[0];
        s5 = s5 > 0.f ? s5 : 0.f;
        float xo = Wout[0] * s5 + bout[0];
        float ls = (xo >= 0.f) ? -log1pf(expf(-xo)) : (xo - log1pf(expf(xo)));
        out[node] = ls;
    }
}

// ---------------- launch ----------------
extern "C" void kernel_launch(void* const* d_in, const int* in_sizes, int n_in,
                              void* d_out, int out_size)
{
    const float* x    = (const float*)d_in[0];
    const int*   ei   = (const int*)d_in[1];
    const int*   src  = ei;
    const int*   dst  = ei + EE;
    const float* Wl1  = (const float*)d_in[3];
    const float* Wr1  = (const float*)d_in[4];
    const float* att1 = (const float*)d_in[5];
    const float* b1   = (const float*)d_in[6];
    const float* Wlin1= (const float*)d_in[7];
    const float* blin1= (const float*)d_in[8];
    const float* Wl2  = (const float*)d_in[9];
    const float* Wr2  = (const float*)d_in[10];
    const float* att2 = (const float*)d_in[11];
    const float* b2   = (const float*)d_in[12];
    const float* Wlin2= (const float*)d_in[13];
    const float* blin2= (const float*)d_in[14];
    const float* t    = (const float*)d_in[15];
    const float* W3   = (const float*)d_in[16];
    const float* b3   = (const float*)d_in[17];
    const float* W4   = (const float*)d_in[18];
    const float* b4   = (const float*)d_in[19];
    const float* W5   = (const float*)d_in[20];
    const float* b5   = (const float*)d_in[21];
    const float* Wout = (const float*)d_in[22];
    const float* bout = (const float*)d_in[23];
    float* out = (float*)d_out;

    // 0: fused layer-1 GEMM + direct bucket scatter (hist+scatter in one pass)
    k_build<<<GEMM1_BLKS + HIST_BLKS, 256>>>(src, dst, x, Wl1, Wr1, Wlin1, blin1);
    // 1: edge layer 1
    k_edge1<<<(NN + 7) / 8, 256>>>(att1, b1, t);
    // 2: layer-2 GEMM (pool is identity) + overflow counter hand-off
    k_gemm2<<<(NN + 255) / 256, 256>>>(Wl2, Wr2, Wlin2, blin2);
    // 3: edge layer 2 + fused MLP head  (<- profiled slot)
    k_edge2h<<<(NN + 7) / 8, 256>>>(att2, b2, t, W3, b3, W4, b4, W5, b5, Wout, bout, out);
}